// round 6
// baseline (speedup 1.0000x reference)
#include <cuda_runtime.h>
#include <cuda_bf16.h>
#include <cstdint>

namespace {

constexpr int   HW    = 36864;        // 192*192
constexpr int   CHW   = 7077888;      // 192*HW
constexpr int   VOFF  = 56623104;     // V plane offset inside kv (8*CHW)
constexpr float SCALE = 0.17677669529663687f;  // 1/sqrt(32)

// smem word offsets (uint32 units)
constexpr int QHI = 0;        // 64 rows x 20 words
constexpr int QLO = 1280;
constexpr int KHI = 2560;
constexpr int KLO = 3840;
constexpr int VHI = 5120;     // 32 rows x 36 words
constexpr int VLO = 6272;
constexpr int SMW = 7424;     // tile words (29696 B)
constexpr int MSTRIDE = 68;   // mask smem row stride (floats)

__device__ __forceinline__ uint32_t pack2(float lo, float hi) {
  // result: low 16 bits = bf16(lo), high 16 bits = bf16(hi)
  uint32_t r;
  asm("cvt.rn.bf16x2.f32 %0, %1, %2;" : "=r"(r) : "f"(hi), "f"(lo));
  return r;
}
__device__ __forceinline__ float bfv(float f) {
  return __bfloat162float(__float2bfloat16_rn(f));
}
__device__ __forceinline__ void mma_bf16(float* c, const uint32_t* a,
                                         uint32_t b0, uint32_t b1) {
  asm volatile(
      "mma.sync.aligned.m16n8k16.row.col.f32.bf16.bf16.f32 "
      "{%0,%1,%2,%3}, {%4,%5,%6,%7}, {%8,%9}, {%0,%1,%2,%3};"
      : "+f"(c[0]), "+f"(c[1]), "+f"(c[2]), "+f"(c[3])
      : "r"(a[0]), "r"(a[1]), "r"(a[2]), "r"(a[3]), "r"(b0), "r"(b1));
}
// Q/K tile addressing: row-stride 20 words, word index XOR-swizzled by row bits.
// Fragment reads (rows 8j+g, word 8ks+t) are conflict-free; staging stores 2-way.
__device__ __forceinline__ int qkw(int r, int w) {
  return r * 20 + (w ^ (((r >> 3) & 3) << 2));
}
__device__ __forceinline__ float felem(float4 a, int j) {
  return (j == 0) ? a.x : (j == 1) ? a.y : (j == 2) ? a.z : a.w;
}

}  // namespace

__global__ __launch_bounds__(128, 4) void winattn_mma2(
    const float* __restrict__ kv, const float* __restrict__ q,
    const float* __restrict__ mask, float* __restrict__ out) {
  __shared__ __align__(16) uint32_t sm[SMW];
  __shared__ __align__(16) float smask[64 * MSTRIDE];   // 17408 B

  const int tid = threadIdx.x;
  const int wid = tid >> 5;
  const int lid = tid & 31;

  // CTA = (win, b): 8 consecutive CTAs share one mask window (L2 reuse on load)
  const int blk = blockIdx.x;
  const int win = blk >> 3;      // 0..575
  const int b   = blk & 7;
  const int u = win / 24;
  const int v = win % 24;

  const int base0 = b * CHW + (u * 8) * 192 + v * 8;

  // ---- dense one-time mask load into smem (row stride 68) ----
  {
    const float4* __restrict__ mg = (const float4*)(mask + win * 4096);
#pragma unroll
    for (int it = 0; it < 8; it++) {
      const int p = it * 128 + tid;      // float4 id 0..1023
      const float4 m = mg[p];
      *(float4*)&smask[(p >> 4) * MSTRIDE + (p & 15) * 4] = m;
    }
  }

  const int g  = lid >> 2;   // 0..7
  const int t  = lid & 3;    // 0..3
  const int m0 = wid * 16;

  for (int d = 0; d < 6; d++) {
    const float* __restrict__ qg = q + base0 + d * 32 * HW;
    const float* __restrict__ kg = kv + base0 + d * 32 * HW;
    const float* __restrict__ vg = kv + VOFF + base0 + d * 32 * HW;
    float* __restrict__ og = out + base0 + d * 32 * HW;

    // ================= stage Q, K (hi/lo split, [row=n][word=ci/2]) ==============
#pragma unroll
    for (int it = 0; it < 2; it++) {
      const int p  = it * 128 + tid;       // 0..255
      const int cw = p >> 4;               // word index = ci/2 (0..15)
      const int h  = (p >> 1) & 7;
      const int wq = p & 1;
      const int n0 = h * 8 + wq * 4;
      const int go = cw * 2 * HW + h * 192 + wq * 4;

      float4 a0 = *(const float4*)(qg + go);
      float4 a1 = *(const float4*)(qg + go + HW);
#pragma unroll
      for (int j = 0; j < 4; j++) {
        const float f0 = felem(a0, j), f1 = felem(a1, j);
        const int w = qkw(n0 + j, cw);
        sm[QHI + w] = pack2(f0, f1);
        sm[QLO + w] = pack2(f0 - bfv(f0), f1 - bfv(f1));
      }
      a0 = *(const float4*)(kg + go);
      a1 = *(const float4*)(kg + go + HW);
#pragma unroll
      for (int j = 0; j < 4; j++) {
        const float f0 = felem(a0, j), f1 = felem(a1, j);
        const int w = qkw(n0 + j, cw);
        sm[KHI + w] = pack2(f0, f1);
        sm[KLO + w] = pack2(f0 - bfv(f0), f1 - bfv(f1));
      }
    }
    // ================= stage V transposed: [row=ci][word=key/2], stride 36 =======
#pragma unroll
    for (int it = 0; it < 4; it++) {
      const int p  = it * 128 + tid;       // 0..511
      const int ci = p >> 4;
      const int h  = (p >> 1) & 7;
      const int wq = p & 1;
      const int n0 = h * 8 + wq * 4;
      const float4 a = *(const float4*)(vg + ci * HW + h * 192 + wq * 4);
      uint2 hp, lp;
      hp.x = pack2(a.x, a.y);
      hp.y = pack2(a.z, a.w);
      lp.x = pack2(a.x - bfv(a.x), a.y - bfv(a.y));
      lp.y = pack2(a.z - bfv(a.z), a.w - bfv(a.w));
      *(uint2*)&sm[VHI + ci * 36 + (n0 >> 1)] = hp;
      *(uint2*)&sm[VLO + ci * 36 + (n0 >> 1)] = lp;
    }
    __syncthreads();

    // ================= QK^T : warp owns rows m0..m0+15 ===========================
    uint32_t aqh[2][4], aql[2][4];
#pragma unroll
    for (int ks = 0; ks < 2; ks++) {
      aqh[ks][0] = sm[QHI + qkw(m0 + g,     ks * 8 + t)];
      aqh[ks][1] = sm[QHI + qkw(m0 + g + 8, ks * 8 + t)];
      aqh[ks][2] = sm[QHI + qkw(m0 + g,     ks * 8 + 4 + t)];
      aqh[ks][3] = sm[QHI + qkw(m0 + g + 8, ks * 8 + 4 + t)];
      aql[ks][0] = sm[QLO + qkw(m0 + g,     ks * 8 + t)];
      aql[ks][1] = sm[QLO + qkw(m0 + g + 8, ks * 8 + t)];
      aql[ks][2] = sm[QLO + qkw(m0 + g,     ks * 8 + 4 + t)];
      aql[ks][3] = sm[QLO + qkw(m0 + g + 8, ks * 8 + 4 + t)];
    }

    float c[8][4];
#pragma unroll
    for (int j = 0; j < 8; j++)
#pragma unroll
      for (int i = 0; i < 4; i++) c[j][i] = 0.f;

#pragma unroll
    for (int j = 0; j < 8; j++) {          // n-tile: cols 8j..8j+7
      const int rb = j * 8 + g;
#pragma unroll
      for (int ks = 0; ks < 2; ks++) {
        const uint32_t bh0 = sm[KHI + qkw(rb, ks * 8 + t)];
        const uint32_t bh1 = sm[KHI + qkw(rb, ks * 8 + 4 + t)];
        const uint32_t bl0 = sm[KLO + qkw(rb, ks * 8 + t)];
        const uint32_t bl1 = sm[KLO + qkw(rb, ks * 8 + 4 + t)];
        mma_bf16(c[j], aqh[ks], bh0, bh1);
        mma_bf16(c[j], aqh[ks], bl0, bl1);
        mma_bf16(c[j], aql[ks], bh0, bh1);
      }
    }

    // ================= softmax (rows m0+g, m0+g+8; mask from smem) ===============
    const float* __restrict__ mr0 = &smask[(m0 + g) * MSTRIDE + 2 * t];
    const float* __restrict__ mr1 = mr0 + 8 * MSTRIDE;
    float sum0 = 0.f, sum1 = 0.f;
#pragma unroll
    for (int j = 0; j < 8; j++) {
      const float2 mv0 = *(const float2*)(mr0 + j * 8);
      const float2 mv1 = *(const float2*)(mr1 + j * 8);
      float e;
      e = __expf(fmaf(c[j][0], SCALE, mv0.x)); c[j][0] = e; sum0 += e;
      e = __expf(fmaf(c[j][1], SCALE, mv0.y)); c[j][1] = e; sum0 += e;
      e = __expf(fmaf(c[j][2], SCALE, mv1.x)); c[j][2] = e; sum1 += e;
      e = __expf(fmaf(c[j][3], SCALE, mv1.y)); c[j][3] = e; sum1 += e;
    }
    sum0 += __shfl_xor_sync(0xffffffffu, sum0, 1);
    sum0 += __shfl_xor_sync(0xffffffffu, sum0, 2);
    sum1 += __shfl_xor_sync(0xffffffffu, sum1, 1);
    sum1 += __shfl_xor_sync(0xffffffffu, sum1, 2);
    const float inv0 = 1.0f / sum0;
    const float inv1 = 1.0f / sum1;

    // P fragments (S accumulator layout == PV A-fragment layout), hi/lo split
    uint32_t aph[4][4], apl[4][4];
#pragma unroll
    for (int ks = 0; ks < 4; ks++) {
      const float* p0 = c[2 * ks];
      const float* p1 = c[2 * ks + 1];
      aph[ks][0] = pack2(p0[0], p0[1]);
      aph[ks][1] = pack2(p0[2], p0[3]);
      aph[ks][2] = pack2(p1[0], p1[1]);
      aph[ks][3] = pack2(p1[2], p1[3]);
      apl[ks][0] = pack2(p0[0] - bfv(p0[0]), p0[1] - bfv(p0[1]));
      apl[ks][1] = pack2(p0[2] - bfv(p0[2]), p0[3] - bfv(p0[3]));
      apl[ks][2] = pack2(p1[0] - bfv(p1[0]), p1[1] - bfv(p1[1]));
      apl[ks][3] = pack2(p1[2] - bfv(p1[2]), p1[3] - bfv(p1[3]));
    }
    __syncthreads();   // all warps done reading Q/K smem before O staging reuses it

    // ================= O = P V ===================================================
    float o[4][4];
#pragma unroll
    for (int jn = 0; jn < 4; jn++)
#pragma unroll
      for (int i = 0; i < 4; i++) o[jn][i] = 0.f;

#pragma unroll
    for (int jn = 0; jn < 4; jn++) {       // channel tile 8jn..8jn+7
      const int rv = (jn * 8 + g) * 36;
#pragma unroll
      for (int ks = 0; ks < 4; ks++) {     // key step 16ks..16ks+15
        const uint32_t bh0 = sm[VHI + rv + ks * 8 + t];
        const uint32_t bh1 = sm[VHI + rv + ks * 8 + 4 + t];
        const uint32_t bl0 = sm[VLO + rv + ks * 8 + t];
        const uint32_t bl1 = sm[VLO + rv + ks * 8 + 4 + t];
        mma_bf16(o[jn], aph[ks], bh0, bh1);
        mma_bf16(o[jn], aph[ks], bl0, bl1);
        mma_bf16(o[jn], apl[ks], bh0, bh1);
      }
    }

    // stage O: [ch][n] stride 68 floats (conflict-free writes and float4 reads)
    float* __restrict__ sO = (float*)sm;
#pragma unroll
    for (int jn = 0; jn < 4; jn++) {
      const int ch = jn * 8 + 2 * t;
      sO[ch * 68 + m0 + g]           = o[jn][0] * inv0;
      sO[(ch + 1) * 68 + m0 + g]     = o[jn][1] * inv0;
      sO[ch * 68 + m0 + g + 8]       = o[jn][2] * inv1;
      sO[(ch + 1) * 68 + m0 + g + 8] = o[jn][3] * inv1;
    }
    __syncthreads();

    // ================= coalesced global store ====================================
#pragma unroll
    for (int it = 0; it < 4; it++) {
      const int p  = it * 128 + tid;
      const int ci = p >> 4;
      const int h  = (p >> 1) & 7;
      const int wq = p & 1;
      const int n0 = h * 8 + wq * 4;
      const float4 a = *(const float4*)&sO[ci * 68 + n0];
      *(float4*)(og + ci * HW + h * 192 + wq * 4) = a;
    }
    __syncthreads();   // protect sO region before next head's Q/K staging
  }
}

extern "C" void kernel_launch(void* const* d_in, const int* in_sizes, int n_in,
                              void* d_out, int out_size) {
  const float* kv = nullptr;
  const float* q = nullptr;
  const float* mask = nullptr;
  for (int i = 0; i < n_in; i++) {
    if (in_sizes[i] == 113246208) kv = (const float*)d_in[i];
    else if (in_sizes[i] == 56623104) q = (const float*)d_in[i];
    else if (in_sizes[i] == 2359296) mask = (const float*)d_in[i];
  }
  if (!kv)   kv   = (const float*)d_in[0];
  if (!q)    q    = (const float*)d_in[1];
  if (!mask) mask = (const float*)d_in[2];
  winattn_mma2<<<4608, 128>>>(kv, q, mask, (float*)d_out);
}

// round 7
// speedup vs baseline: 1.1763x; 1.1763x over previous
#include <cuda_runtime.h>
#include <cuda.h>
#include <cuda_bf16.h>
#include <cstdint>

namespace {

constexpr int   HW    = 36864;        // 192*192
constexpr float SCALE = 0.17677669529663687f;  // 1/sqrt(32)

// dynamic smem layout (float units)
//   [0..32)        mbarrier + pad (128B)
//   [32..2080)     rawQ  [c=32][h=8][w=8] fp32 (8KB)
//   [2080..4128)   rawK
//   [4128..6176)   rawV
//   [6176..)       tile words (uint32): 7424 words
constexpr int RAWQ = 32;
constexpr int RAWK = 2080;
constexpr int RAWV = 4128;
constexpr int TILE = 6176;
constexpr int SMEM_BYTES = (TILE + 7424) * 4;   // 54400

// tile word offsets (within sm[])
constexpr int QHI = 0;        // 64 rows x 20 words
constexpr int QLO = 1280;
constexpr int KHI = 2560;
constexpr int KLO = 3840;
constexpr int VHI = 5120;     // 32 rows x 36 words
constexpr int VLO = 6272;

__device__ __forceinline__ uint32_t s2u(const void* p) {
  uint32_t a;
  asm("{ .reg .u64 t; cvta.to.shared.u64 t, %1; cvt.u32.u64 %0, t; }" : "=r"(a) : "l"(p));
  return a;
}
__device__ __forceinline__ uint32_t pack2(float lo, float hi) {
  uint32_t r;
  asm("cvt.rn.bf16x2.f32 %0, %1, %2;" : "=r"(r) : "f"(hi), "f"(lo));
  return r;
}
__device__ __forceinline__ float bfv(float f) {
  return __bfloat162float(__float2bfloat16_rn(f));
}
__device__ __forceinline__ void mma_bf16(float* c, const uint32_t* a,
                                         uint32_t b0, uint32_t b1) {
  asm volatile(
      "mma.sync.aligned.m16n8k16.row.col.f32.bf16.bf16.f32 "
      "{%0,%1,%2,%3}, {%4,%5,%6,%7}, {%8,%9}, {%0,%1,%2,%3};"
      : "+f"(c[0]), "+f"(c[1]), "+f"(c[2]), "+f"(c[3])
      : "r"(a[0]), "r"(a[1]), "r"(a[2]), "r"(a[3]), "r"(b0), "r"(b1));
}
__device__ __forceinline__ int qkw(int r, int w) {
  return r * 20 + (w ^ (((r >> 3) & 3) << 2));
}
__device__ __forceinline__ float felem(float4 a, int j) {
  return (j == 0) ? a.x : (j == 1) ? a.y : (j == 2) ? a.z : a.w;
}
__device__ __forceinline__ void bar_init(uint32_t bar, uint32_t cnt) {
  asm volatile("mbarrier.init.shared.b64 [%0], %1;" :: "r"(bar), "r"(cnt) : "memory");
}
__device__ __forceinline__ void bar_expect(uint32_t bar, uint32_t bytes) {
  asm volatile("mbarrier.arrive.expect_tx.shared.b64 _, [%0], %1;"
               :: "r"(bar), "r"(bytes) : "memory");
}
__device__ __forceinline__ void bar_wait(uint32_t bar, uint32_t parity) {
  uint32_t done;
  asm volatile(
      "{\n\t.reg .pred p;\n\t"
      "mbarrier.try_wait.parity.acquire.cta.shared::cta.b64 p, [%1], %2;\n\t"
      "selp.b32 %0, 1, 0, p;\n\t}"
      : "=r"(done) : "r"(bar), "r"(parity) : "memory");
  if (!done) {
    asm volatile(
        "{\n\t.reg .pred P1;\n\t"
        "W_%=:\n\t"
        "mbarrier.try_wait.parity.acquire.cta.shared::cta.b64 P1, [%0], %1, 0x989680;\n\t"
        "@P1 bra.uni D_%=;\n\t"
        "bra.uni W_%=;\n\t"
        "D_%=:\n\t}"
        :: "r"(bar), "r"(parity) : "memory");
  }
}
__device__ __forceinline__ void tma3d(uint32_t dst, const CUtensorMap* map,
                                      int x, int y, int z, uint32_t bar) {
  asm volatile(
      "cp.async.bulk.tensor.3d.shared::cta.global.tile.mbarrier::complete_tx::bytes "
      "[%0], [%1, {%2, %3, %4}], [%5];"
      :: "r"(dst), "l"(map), "r"(x), "r"(y), "r"(z), "r"(bar) : "memory");
}

}  // namespace

__global__ __launch_bounds__(128, 4) void winattn_tma(
    const __grid_constant__ CUtensorMap mapQ,
    const __grid_constant__ CUtensorMap mapKV,
    const float* __restrict__ mask, float* __restrict__ out,
    float* __restrict__ outDummy) {
  extern __shared__ float dyn[];
  float* __restrict__ rawQ = dyn + RAWQ;
  float* __restrict__ rawK = dyn + RAWK;
  float* __restrict__ rawV = dyn + RAWV;
  uint32_t* __restrict__ sm = (uint32_t*)(dyn + TILE);

  const int tid = threadIdx.x;
  const int wid = tid >> 5;
  const int lid = tid & 31;

  // block decode: 48 consecutive CTAs (8 b x 6 d) share one mask window (L2 reuse)
  const int blk = blockIdx.x;
  const int win = blk / 48;
  const int rem = blk % 48;
  const int b = rem / 6;
  const int d = rem % 6;
  const int u = win / 24;
  const int v = win % 24;

  const uint32_t mbar = s2u(dyn);
  if (tid == 0) bar_init(mbar, 1);
  __syncthreads();
  if (tid == 0) {
    const int zc = b * 192 + d * 32;
    bar_expect(mbar, 3 * 8192);
    tma3d(s2u(rawQ), &mapQ, v * 8, u * 8, zc, mbar);
    tma3d(s2u(rawK), &mapKV, v * 8, u * 8, zc, mbar);
    tma3d(s2u(rawV), &mapKV, v * 8, u * 8, 1536 + zc, mbar);
  }

  const int base = b * 6 * 32 * HW + d * 32 * HW + (u * 8) * 192 + v * 8;
  float* __restrict__ og = out + base;

  bar_wait(mbar, 0);

  // ================= stage Q, K from raw smem (hi/lo split) ======================
#pragma unroll
  for (int it = 0; it < 2; it++) {
    const int p  = it * 128 + tid;       // 0..255
    const int cw = p >> 4;               // word index = ci/2 (0..15)
    const int h  = (p >> 1) & 7;
    const int wq = p & 1;
    const int n0 = h * 8 + wq * 4;
    const int ro = (2 * cw) * 64 + h * 8 + wq * 4;

    float4 a0 = *(const float4*)(rawQ + ro);
    float4 a1 = *(const float4*)(rawQ + ro + 64);
#pragma unroll
    for (int j = 0; j < 4; j++) {
      const float f0 = felem(a0, j), f1 = felem(a1, j);
      const int w = qkw(n0 + j, cw);
      sm[QHI + w] = pack2(f0, f1);
      sm[QLO + w] = pack2(f0 - bfv(f0), f1 - bfv(f1));
    }
    a0 = *(const float4*)(rawK + ro);
    a1 = *(const float4*)(rawK + ro + 64);
#pragma unroll
    for (int j = 0; j < 4; j++) {
      const float f0 = felem(a0, j), f1 = felem(a1, j);
      const int w = qkw(n0 + j, cw);
      sm[KHI + w] = pack2(f0, f1);
      sm[KLO + w] = pack2(f0 - bfv(f0), f1 - bfv(f1));
    }
  }
  // ================= stage V transposed from raw smem ============================
#pragma unroll
  for (int it = 0; it < 4; it++) {
    const int p  = it * 128 + tid;       // 0..511
    const int ci = p >> 4;
    const int h  = (p >> 1) & 7;
    const int wq = p & 1;
    const int n0 = h * 8 + wq * 4;
    const float4 a = *(const float4*)(rawV + ci * 64 + h * 8 + wq * 4);
    uint2 hp, lp;
    hp.x = pack2(a.x, a.y);
    hp.y = pack2(a.z, a.w);
    lp.x = pack2(a.x - bfv(a.x), a.y - bfv(a.y));
    lp.y = pack2(a.z - bfv(a.z), a.w - bfv(a.w));
    *(uint2*)&sm[VHI + ci * 36 + (n0 >> 1)] = hp;
    *(uint2*)&sm[VLO + ci * 36 + (n0 >> 1)] = lp;
  }
  __syncthreads();

  // ================= QK^T : warp owns rows m0..m0+15 =============================
  const int g  = lid >> 2;   // 0..7
  const int t  = lid & 3;    // 0..3
  const int m0 = wid * 16;

  uint32_t aqh[2][4], aql[2][4];
#pragma unroll
  for (int ks = 0; ks < 2; ks++) {
    aqh[ks][0] = sm[QHI + qkw(m0 + g,     ks * 8 + t)];
    aqh[ks][1] = sm[QHI + qkw(m0 + g + 8, ks * 8 + t)];
    aqh[ks][2] = sm[QHI + qkw(m0 + g,     ks * 8 + 4 + t)];
    aqh[ks][3] = sm[QHI + qkw(m0 + g + 8, ks * 8 + 4 + t)];
    aql[ks][0] = sm[QLO + qkw(m0 + g,     ks * 8 + t)];
    aql[ks][1] = sm[QLO + qkw(m0 + g + 8, ks * 8 + t)];
    aql[ks][2] = sm[QLO + qkw(m0 + g,     ks * 8 + 4 + t)];
    aql[ks][3] = sm[QLO + qkw(m0 + g + 8, ks * 8 + 4 + t)];
  }

  float c[8][4];
#pragma unroll
  for (int j = 0; j < 8; j++)
#pragma unroll
    for (int i = 0; i < 4; i++) c[j][i] = 0.f;

#pragma unroll
  for (int j = 0; j < 8; j++) {          // n-tile: cols 8j..8j+7
    const int rb = j * 8 + g;
#pragma unroll
    for (int ks = 0; ks < 2; ks++) {
      const uint32_t bh0 = sm[KHI + qkw(rb, ks * 8 + t)];
      const uint32_t bh1 = sm[KHI + qkw(rb, ks * 8 + 4 + t)];
      const uint32_t bl0 = sm[KLO + qkw(rb, ks * 8 + t)];
      const uint32_t bl1 = sm[KLO + qkw(rb, ks * 8 + 4 + t)];
      mma_bf16(c[j], aqh[ks], bh0, bh1);
      mma_bf16(c[j], aqh[ks], bl0, bl1);
      mma_bf16(c[j], aql[ks], bh0, bh1);
    }
  }

  // ================= softmax (rows m0+g, m0+g+8; mask from L2) ===================
  const float* __restrict__ mrow = mask + win * 4096 + (m0 + g) * 64 + 2 * t;
  float sum0 = 0.f, sum1 = 0.f;
#pragma unroll
  for (int j = 0; j < 8; j++) {
    const float2 mv0 = *(const float2*)(mrow + j * 8);
    const float2 mv1 = *(const float2*)(mrow + 512 + j * 8);
    float e;
    e = __expf(fmaf(c[j][0], SCALE, mv0.x)); c[j][0] = e; sum0 += e;
    e = __expf(fmaf(c[j][1], SCALE, mv0.y)); c[j][1] = e; sum0 += e;
    e = __expf(fmaf(c[j][2], SCALE, mv1.x)); c[j][2] = e; sum1 += e;
    e = __expf(fmaf(c[j][3], SCALE, mv1.y)); c[j][3] = e; sum1 += e;
  }
  sum0 += __shfl_xor_sync(0xffffffffu, sum0, 1);
  sum0 += __shfl_xor_sync(0xffffffffu, sum0, 2);
  sum1 += __shfl_xor_sync(0xffffffffu, sum1, 1);
  sum1 += __shfl_xor_sync(0xffffffffu, sum1, 2);
  const float inv0 = 1.0f / sum0;
  const float inv1 = 1.0f / sum1;

  // P fragments (S accumulator layout == PV A-fragment layout), hi/lo split
  uint32_t aph[4][4], apl[4][4];
#pragma unroll
  for (int ks = 0; ks < 4; ks++) {
    const float* p0 = c[2 * ks];
    const float* p1 = c[2 * ks + 1];
    aph[ks][0] = pack2(p0[0], p0[1]);
    aph[ks][1] = pack2(p0[2], p0[3]);
    aph[ks][2] = pack2(p1[0], p1[1]);
    aph[ks][3] = pack2(p1[2], p1[3]);
    apl[ks][0] = pack2(p0[0] - bfv(p0[0]), p0[1] - bfv(p0[1]));
    apl[ks][1] = pack2(p0[2] - bfv(p0[2]), p0[3] - bfv(p0[3]));
    apl[ks][2] = pack2(p1[0] - bfv(p1[0]), p1[1] - bfv(p1[1]));
    apl[ks][3] = pack2(p1[2] - bfv(p1[2]), p1[3] - bfv(p1[3]));
  }
  __syncthreads();   // all warps done reading Q/K smem before O staging reuses it

  // ================= O = P V =====================================================
  float o[4][4];
#pragma unroll
  for (int jn = 0; jn < 4; jn++)
#pragma unroll
    for (int i = 0; i < 4; i++) o[jn][i] = 0.f;

#pragma unroll
  for (int jn = 0; jn < 4; jn++) {       // channel tile 8jn..8jn+7
    const int rv = (jn * 8 + g) * 36;
#pragma unroll
    for (int ks = 0; ks < 4; ks++) {     // key step 16ks..16ks+15
      const uint32_t bh0 = sm[VHI + rv + ks * 8 + t];
      const uint32_t bh1 = sm[VHI + rv + ks * 8 + 4 + t];
      const uint32_t bl0 = sm[VLO + rv + ks * 8 + t];
      const uint32_t bl1 = sm[VLO + rv + ks * 8 + 4 + t];
      mma_bf16(o[jn], aph[ks], bh0, bh1);
      mma_bf16(o[jn], aph[ks], bl0, bl1);
      mma_bf16(o[jn], apl[ks], bh0, bh1);
    }
  }

  // stage O: [ch][n] stride 68 floats (conflict-free writes and float4 reads)
  float* __restrict__ sO = (float*)sm;
#pragma unroll
  for (int jn = 0; jn < 4; jn++) {
    const int ch = jn * 8 + 2 * t;
    sO[ch * 68 + m0 + g]           = o[jn][0] * inv0;
    sO[(ch + 1) * 68 + m0 + g]     = o[jn][1] * inv0;
    sO[ch * 68 + m0 + g + 8]       = o[jn][2] * inv1;
    sO[(ch + 1) * 68 + m0 + g + 8] = o[jn][3] * inv1;
  }
  __syncthreads();

  // ================= coalesced global store ======================================
#pragma unroll
  for (int it = 0; it < 4; it++) {
    const int p  = it * 128 + tid;
    const int ci = p >> 4;
    const int h  = (p >> 1) & 7;
    const int wq = p & 1;
    const int n0 = h * 8 + wq * 4;
    const float4 a = *(const float4*)&sO[ci * 68 + n0];
    *(float4*)(og + ci * HW + h * 192 + wq * 4) = a;
  }
}

typedef CUresult (*EncodeFn)(CUtensorMap*, CUtensorMapDataType, cuuint32_t, void*,
                             const cuuint64_t*, const cuuint64_t*, const cuuint32_t*,
                             const cuuint32_t*, CUtensorMapInterleave, CUtensorMapSwizzle,
                             CUtensorMapL2promotion, CUtensorMapFloatOOBfill);

extern "C" void kernel_launch(void* const* d_in, const int* in_sizes, int n_in,
                              void* d_out, int out_size) {
  const float* kv = nullptr;
  const float* q = nullptr;
  const float* mask = nullptr;
  for (int i = 0; i < n_in; i++) {
    if (in_sizes[i] == 113246208) kv = (const float*)d_in[i];
    else if (in_sizes[i] == 56623104) q = (const float*)d_in[i];
    else if (in_sizes[i] == 2359296) mask = (const float*)d_in[i];
  }
  if (!kv)   kv   = (const float*)d_in[0];
  if (!q)    q    = (const float*)d_in[1];
  if (!mask) mask = (const float*)d_in[2];

  // Tensor maps: dim0 = W (contiguous), dim1 = H, dim2 = flattened (B*C or 2*B*C)
  EncodeFn encode = nullptr;
  cudaDriverEntryPointQueryResult qres;
  cudaGetDriverEntryPoint("cuTensorMapEncodeTiled", (void**)&encode,
                          cudaEnableDefault, &qres);

  CUtensorMap mapQ{}, mapKV{};
  {
    cuuint64_t dims[3]    = {192, 192, 1536};
    cuuint64_t strides[2] = {192 * 4ull, (cuuint64_t)HW * 4ull};
    cuuint32_t box[3]     = {8, 8, 32};
    cuuint32_t es[3]      = {1, 1, 1};
    encode(&mapQ, CU_TENSOR_MAP_DATA_TYPE_FLOAT32, 3, (void*)q,
           dims, strides, box, es,
           CU_TENSOR_MAP_INTERLEAVE_NONE, CU_TENSOR_MAP_SWIZZLE_NONE,
           CU_TENSOR_MAP_L2_PROMOTION_L2_128B, CU_TENSOR_MAP_FLOAT_OOB_FILL_NONE);
  }
  {
    cuuint64_t dims[3]    = {192, 192, 3072};
    cuuint64_t strides[2] = {192 * 4ull, (cuuint64_t)HW * 4ull};
    cuuint32_t box[3]     = {8, 8, 32};
    cuuint32_t es[3]      = {1, 1, 1};
    encode(&mapKV, CU_TENSOR_MAP_DATA_TYPE_FLOAT32, 3, (void*)kv,
           dims, strides, box, es,
           CU_TENSOR_MAP_INTERLEAVE_NONE, CU_TENSOR_MAP_SWIZZLE_NONE,
           CU_TENSOR_MAP_L2_PROMOTION_L2_128B, CU_TENSOR_MAP_FLOAT_OOB_FILL_NONE);
  }

  cudaFuncSetAttribute(winattn_tma, cudaFuncAttributeMaxDynamicSharedMemorySize,
                       SMEM_BYTES);
  winattn_tma<<<27648, 128, SMEM_BYTES>>>(mapQ, mapKV, mask, (float*)d_out, nullptr);
}

// round 9
// speedup vs baseline: 1.3560x; 1.1528x over previous
#include <cuda_runtime.h>
#include <cuda.h>
#include <cuda_bf16.h>
#include <cstdint>

namespace {

constexpr int   HW    = 36864;        // 192*192
constexpr float SCALE = 0.17677669529663687f;  // 1/sqrt(32)

// dynamic smem layout (float units)
//   [0..32)        mbarrier + pad (128B)
//   [32..2080)     rawQ  [c=32][h=8][w=8] fp32 (8KB)   } dead after conversion;
//   [2080..4128)   rawK                                 } reused for mask (64 x 68)
//   [4128..6176)   rawV
//   [6176..)       tile words (uint32): 7424 words; words [0..2048) reused for sO
constexpr int RAWQ = 32;
constexpr int RAWK = 2080;
constexpr int RAWV = 4128;
constexpr int MASKS = 32;             // mask smem base (floats), stride 68
constexpr int TILE = 6176;
constexpr int SMEM_BYTES = (TILE + 7424) * 4;   // 54400

// tile word offsets (within sm[])
constexpr int QHI = 0;        // 64 rows x 20 words
constexpr int QLO = 1280;
constexpr int KHI = 2560;
constexpr int KLO = 3840;
constexpr int VHI = 5120;     // 32 rows x 36 words
constexpr int VLO = 6272;

__device__ __forceinline__ uint32_t s2u(const void* p) {
  uint32_t a;
  asm("{ .reg .u64 t; cvta.to.shared.u64 t, %1; cvt.u32.u64 %0, t; }" : "=r"(a) : "l"(p));
  return a;
}
__device__ __forceinline__ uint32_t pack2(float lo, float hi) {
  uint32_t r;
  asm("cvt.rn.bf16x2.f32 %0, %1, %2;" : "=r"(r) : "f"(hi), "f"(lo));
  return r;
}
__device__ __forceinline__ float bfv(float f) {
  return __bfloat162float(__float2bfloat16_rn(f));
}
__device__ __forceinline__ void mma_bf16(float* c, const uint32_t* a,
                                         uint32_t b0, uint32_t b1) {
  asm volatile(
      "mma.sync.aligned.m16n8k16.row.col.f32.bf16.bf16.f32 "
      "{%0,%1,%2,%3}, {%4,%5,%6,%7}, {%8,%9}, {%0,%1,%2,%3};"
      : "+f"(c[0]), "+f"(c[1]), "+f"(c[2]), "+f"(c[3])
      : "r"(a[0]), "r"(a[1]), "r"(a[2]), "r"(a[3]), "r"(b0), "r"(b1));
}
__device__ __forceinline__ int qkw(int r, int w) {
  return r * 20 + (w ^ (((r >> 3) & 3) << 2));
}
__device__ __forceinline__ float felem(float4 a, int j) {
  return (j == 0) ? a.x : (j == 1) ? a.y : (j == 2) ? a.z : a.w;
}
__device__ __forceinline__ void bar_init(uint32_t bar, uint32_t cnt) {
  asm volatile("mbarrier.init.shared.b64 [%0], %1;" :: "r"(bar), "r"(cnt) : "memory");
}
__device__ __forceinline__ void bar_expect(uint32_t bar, uint32_t bytes) {
  asm volatile("mbarrier.arrive.expect_tx.shared.b64 _, [%0], %1;"
               :: "r"(bar), "r"(bytes) : "memory");
}
__device__ __forceinline__ void bar_wait(uint32_t bar, uint32_t parity) {
  uint32_t done;
  asm volatile(
      "{\n\t.reg .pred p;\n\t"
      "mbarrier.try_wait.parity.acquire.cta.shared::cta.b64 p, [%1], %2;\n\t"
      "selp.b32 %0, 1, 0, p;\n\t}"
      : "=r"(done) : "r"(bar), "r"(parity) : "memory");
  if (!done) {
    asm volatile(
        "{\n\t.reg .pred P1;\n\t"
        "W_%=:\n\t"
        "mbarrier.try_wait.parity.acquire.cta.shared::cta.b64 P1, [%0], %1, 0x989680;\n\t"
        "@P1 bra.uni D_%=;\n\t"
        "bra.uni W_%=;\n\t"
        "D_%=:\n\t}"
        :: "r"(bar), "r"(parity) : "memory");
  }
}
__device__ __forceinline__ void tma3d(uint32_t dst, const CUtensorMap* map,
                                      int x, int y, int z, uint32_t bar) {
  asm volatile(
      "cp.async.bulk.tensor.3d.shared::cta.global.tile.mbarrier::complete_tx::bytes "
      "[%0], [%1, {%2, %3, %4}], [%5];"
      :: "r"(dst), "l"(map), "r"(x), "r"(y), "r"(z), "r"(bar) : "memory");
}
__device__ __forceinline__ void tma3d_store(const CUtensorMap* map,
                                            int x, int y, int z, uint32_t src) {
  asm volatile(
      "cp.async.bulk.tensor.3d.global.shared::cta.tile.bulk_group "
      "[%0, {%1, %2, %3}], [%4];"
      :: "l"(map), "r"(x), "r"(y), "r"(z), "r"(src) : "memory");
}

}  // namespace

__global__ __launch_bounds__(128, 4) void winattn_tma3(
    const __grid_constant__ CUtensorMap mapQ,
    const __grid_constant__ CUtensorMap mapKV,
    const __grid_constant__ CUtensorMap mapO,
    const float* __restrict__ mask) {
  extern __shared__ float dyn[];
  float* __restrict__ rawQ = dyn + RAWQ;
  float* __restrict__ rawK = dyn + RAWK;
  float* __restrict__ rawV = dyn + RAWV;
  float* __restrict__ maskSm = dyn + MASKS;       // stride 68, reuses raw region
  uint32_t* __restrict__ sm = (uint32_t*)(dyn + TILE);

  const int tid = threadIdx.x;
  const int wid = tid >> 5;
  const int lid = tid & 31;

  // block decode: 48 consecutive CTAs (8 b x 6 d) share one mask window (L2 reuse)
  const int blk = blockIdx.x;
  const int win = blk / 48;
  const int rem = blk % 48;
  const int b = rem / 6;
  const int d = rem % 6;
  const int u = win / 24;
  const int v = win % 24;
  const int zc = b * 192 + d * 32;

  const uint32_t mbar = s2u(dyn);
  if (tid == 0) bar_init(mbar, 1);
  __syncthreads();
  if (tid == 0) {
    bar_expect(mbar, 3 * 8192);
    tma3d(s2u(rawQ), &mapQ, v * 8, u * 8, zc, mbar);
    tma3d(s2u(rawK), &mapKV, v * 8, u * 8, zc, mbar);
    tma3d(s2u(rawV), &mapKV, v * 8, u * 8, 1536 + zc, mbar);
  }

  bar_wait(mbar, 0);

  // ================= stage Q, K from raw smem (hi/lo split) ======================
#pragma unroll
  for (int it = 0; it < 2; it++) {
    const int p  = it * 128 + tid;       // 0..255
    const int cw = p >> 4;               // word index = ci/2 (0..15)
    const int h  = (p >> 1) & 7;
    const int wq = p & 1;
    const int n0 = h * 8 + wq * 4;
    const int ro = (2 * cw) * 64 + h * 8 + wq * 4;

    float4 a0 = *(const float4*)(rawQ + ro);
    float4 a1 = *(const float4*)(rawQ + ro + 64);
#pragma unroll
    for (int j = 0; j < 4; j++) {
      const float f0 = felem(a0, j), f1 = felem(a1, j);
      const int w = qkw(n0 + j, cw);
      sm[QHI + w] = pack2(f0, f1);
      sm[QLO + w] = pack2(f0 - bfv(f0), f1 - bfv(f1));
    }
    a0 = *(const float4*)(rawK + ro);
    a1 = *(const float4*)(rawK + ro + 64);
#pragma unroll
    for (int j = 0; j < 4; j++) {
      const float f0 = felem(a0, j), f1 = felem(a1, j);
      const int w = qkw(n0 + j, cw);
      sm[KHI + w] = pack2(f0, f1);
      sm[KLO + w] = pack2(f0 - bfv(f0), f1 - bfv(f1));
    }
  }
  // ================= stage V transposed from raw smem ============================
#pragma unroll
  for (int it = 0; it < 4; it++) {
    const int p  = it * 128 + tid;       // 0..511
    const int ci = p >> 4;
    const int h  = (p >> 1) & 7;
    const int wq = p & 1;
    const int n0 = h * 8 + wq * 4;
    const float4 a = *(const float4*)(rawV + ci * 64 + h * 8 + wq * 4);
    uint2 hp, lp;
    hp.x = pack2(a.x, a.y);
    hp.y = pack2(a.z, a.w);
    lp.x = pack2(a.x - bfv(a.x), a.y - bfv(a.y));
    lp.y = pack2(a.z - bfv(a.z), a.w - bfv(a.w));
    *(uint2*)&sm[VHI + ci * 36 + (n0 >> 1)] = hp;
    *(uint2*)&sm[VLO + ci * 36 + (n0 >> 1)] = lp;
  }
  __syncthreads();   // conversion done; raw region is now dead -> mask staging

  const int g  = lid >> 2;   // 0..7
  const int t  = lid & 3;    // 0..3
  const int m0 = wid * 16;

  // ---- each warp dense-stages its OWN 16 mask rows into smem (stride 68) ----
  {
    const float4* __restrict__ mg = (const float4*)(mask + win * 4096);
#pragma unroll
    for (int i = 0; i < 8; i++) {
      const int row = m0 + 2 * i + (lid >> 4);
      const int c4  = lid & 15;
      const float4 m = mg[row * 16 + c4];
      *(float4*)&maskSm[row * 68 + c4 * 4] = m;
    }
    __syncwarp();
  }

  // ================= QK^T : warp owns rows m0..m0+15 =============================
  uint32_t aqh[2][4], aql[2][4];
#pragma unroll
  for (int ks = 0; ks < 2; ks++) {
    aqh[ks][0] = sm[QHI + qkw(m0 + g,     ks * 8 + t)];
    aqh[ks][1] = sm[QHI + qkw(m0 + g + 8, ks * 8 + t)];
    aqh[ks][2] = sm[QHI + qkw(m0 + g,     ks * 8 + 4 + t)];
    aqh[ks][3] = sm[QHI + qkw(m0 + g + 8, ks * 8 + 4 + t)];
    aql[ks][0] = sm[QLO + qkw(m0 + g,     ks * 8 + t)];
    aql[ks][1] = sm[QLO + qkw(m0 + g + 8, ks * 8 + t)];
    aql[ks][2] = sm[QLO + qkw(m0 + g,     ks * 8 + 4 + t)];
    aql[ks][3] = sm[QLO + qkw(m0 + g + 8, ks * 8 + 4 + t)];
  }

  float c[8][4];
#pragma unroll
  for (int j = 0; j < 8; j++)
#pragma unroll
    for (int i = 0; i < 4; i++) c[j][i] = 0.f;

#pragma unroll
  for (int j = 0; j < 8; j++) {          // n-tile: cols 8j..8j+7
    const int rb = j * 8 + g;
#pragma unroll
    for (int ks = 0; ks < 2; ks++) {
      const uint32_t bh0 = sm[KHI + qkw(rb, ks * 8 + t)];
      const uint32_t bh1 = sm[KHI + qkw(rb, ks * 8 + 4 + t)];
      const uint32_t bl0 = sm[KLO + qkw(rb, ks * 8 + t)];
      const uint32_t bl1 = sm[KLO + qkw(rb, ks * 8 + 4 + t)];
      mma_bf16(c[j], aqh[ks], bh0, bh1);
      mma_bf16(c[j], aqh[ks], bl0, bl1);
      mma_bf16(c[j], aql[ks], bh0, bh1);
    }
  }

  // ================= softmax (rows m0+g, m0+g+8; mask from smem) =================
  const float* __restrict__ mr0 = &maskSm[(m0 + g) * 68 + 2 * t];
  const float* __restrict__ mr1 = mr0 + 8 * 68;
  float sum0 = 0.f, sum1 = 0.f;
#pragma unroll
  for (int j = 0; j < 8; j++) {
    const float2 mv0 = *(const float2*)(mr0 + j * 8);
    const float2 mv1 = *(const float2*)(mr1 + j * 8);
    float e;
    e = __expf(fmaf(c[j][0], SCALE, mv0.x)); c[j][0] = e; sum0 += e;
    e = __expf(fmaf(c[j][1], SCALE, mv0.y)); c[j][1] = e; sum0 += e;
    e = __expf(fmaf(c[j][2], SCALE, mv1.x)); c[j][2] = e; sum1 += e;
    e = __expf(fmaf(c[j][3], SCALE, mv1.y)); c[j][3] = e; sum1 += e;
  }
  sum0 += __shfl_xor_sync(0xffffffffu, sum0, 1);
  sum0 += __shfl_xor_sync(0xffffffffu, sum0, 2);
  sum1 += __shfl_xor_sync(0xffffffffu, sum1, 1);
  sum1 += __shfl_xor_sync(0xffffffffu, sum1, 2);
  const float inv0 = 1.0f / sum0;
  const float inv1 = 1.0f / sum1;

  // P fragments (S accumulator layout == PV A-fragment layout), hi/lo split
  uint32_t aph[4][4], apl[4][4];
#pragma unroll
  for (int ks = 0; ks < 4; ks++) {
    const float* p0 = c[2 * ks];
    const float* p1 = c[2 * ks + 1];
    aph[ks][0] = pack2(p0[0], p0[1]);
    aph[ks][1] = pack2(p0[2], p0[3]);
    aph[ks][2] = pack2(p1[0], p1[1]);
    aph[ks][3] = pack2(p1[2], p1[3]);
    apl[ks][0] = pack2(p0[0] - bfv(p0[0]), p0[1] - bfv(p0[1]));
    apl[ks][1] = pack2(p0[2] - bfv(p0[2]), p0[3] - bfv(p0[3]));
    apl[ks][2] = pack2(p1[0] - bfv(p1[0]), p1[1] - bfv(p1[1]));
    apl[ks][3] = pack2(p1[2] - bfv(p1[2]), p1[3] - bfv(p1[3]));
  }
  __syncthreads();   // all warps done reading Q/K smem before sO reuses it

  // ================= O = P V =====================================================
  float o[4][4];
#pragma unroll
  for (int jn = 0; jn < 4; jn++)
#pragma unroll
    for (int i = 0; i < 4; i++) o[jn][i] = 0.f;

#pragma unroll
  for (int jn = 0; jn < 4; jn++) {       // channel tile 8jn..8jn+7
    const int rv = (jn * 8 + g) * 36;
#pragma unroll
    for (int ks = 0; ks < 4; ks++) {     // key step 16ks..16ks+15
      const uint32_t bh0 = sm[VHI + rv + ks * 8 + t];
      const uint32_t bh1 = sm[VHI + rv + ks * 8 + 4 + t];
      const uint32_t bl0 = sm[VLO + rv + ks * 8 + t];
      const uint32_t bl1 = sm[VLO + rv + ks * 8 + 4 + t];
      mma_bf16(o[jn], aph[ks], bh0, bh1);
      mma_bf16(o[jn], aph[ks], bl0, bl1);
      mma_bf16(o[jn], apl[ks], bh0, bh1);
    }
  }

  // ===== stage O dense [c][h][w] fp32 (plain layout, TMA store source) ===========
  float* __restrict__ sO = (float*)sm;   // words [0..2048), overlaps dead Q tiles
#pragma unroll
  for (int jn = 0; jn < 4; jn++) {
    const int ch = jn * 8 + 2 * t;
#pragma unroll
    for (int bb = 0; bb < 2; bb++) {
      sO[(ch + bb) * 64 + m0 + g]     = o[jn][bb] * inv0;
      sO[(ch + bb) * 64 + m0 + g + 8] = o[jn][2 + bb] * inv1;
    }
  }
  __syncthreads();

  // ================= TMA store O =================================================
  if (tid == 0) {
    asm volatile("fence.proxy.async.shared::cta;" ::: "memory");
    tma3d_store(&mapO, v * 8, u * 8, zc, s2u(sO));
    asm volatile("cp.async.bulk.commit_group;" ::: "memory");
    asm volatile("cp.async.bulk.wait_group 0;" ::: "memory");
  }
}

typedef CUresult (*EncodeFn)(CUtensorMap*, CUtensorMapDataType, cuuint32_t, void*,
                             const cuuint64_t*, const cuuint64_t*, const cuuint32_t*,
                             const cuuint32_t*, CUtensorMapInterleave, CUtensorMapSwizzle,
                             CUtensorMapL2promotion, CUtensorMapFloatOOBfill);

extern "C" void kernel_launch(void* const* d_in, const int* in_sizes, int n_in,
                              void* d_out, int out_size) {
  const float* kv = nullptr;
  const float* q = nullptr;
  const float* mask = nullptr;
  for (int i = 0; i < n_in; i++) {
    if (in_sizes[i] == 113246208) kv = (const float*)d_in[i];
    else if (in_sizes[i] == 56623104) q = (const float*)d_in[i];
    else if (in_sizes[i] == 2359296) mask = (const float*)d_in[i];
  }
  if (!kv)   kv   = (const float*)d_in[0];
  if (!q)    q    = (const float*)d_in[1];
  if (!mask) mask = (const float*)d_in[2];

  EncodeFn encode = nullptr;
  cudaDriverEntryPointQueryResult qres;
  cudaGetDriverEntryPoint("cuTensorMapEncodeTiled", (void**)&encode,
                          cudaEnableDefault, &qres);

  cuuint64_t strides[2] = {192 * 4ull, (cuuint64_t)HW * 4ull};
  cuuint32_t box[3]     = {8, 8, 32};
  cuuint32_t es[3]      = {1, 1, 1};

  CUtensorMap mapQ{}, mapKV{}, mapO{};
  {
    cuuint64_t dims[3] = {192, 192, 1536};
    encode(&mapQ, CU_TENSOR_MAP_DATA_TYPE_FLOAT32, 3, (void*)q,
           dims, strides, box, es,
           CU_TENSOR_MAP_INTERLEAVE_NONE, CU_TENSOR_MAP_SWIZZLE_NONE,
           CU_TENSOR_MAP_L2_PROMOTION_L2_128B, CU_TENSOR_MAP_FLOAT_OOB_FILL_NONE);
  }
  {
    cuuint64_t dims[3] = {192, 192, 3072};
    encode(&mapKV, CU_TENSOR_MAP_DATA_TYPE_FLOAT32, 3, (void*)kv,
           dims, strides, box, es,
           CU_TENSOR_MAP_INTERLEAVE_NONE, CU_TENSOR_MAP_SWIZZLE_NONE,
           CU_TENSOR_MAP_L2_PROMOTION_L2_128B, CU_TENSOR_MAP_FLOAT_OOB_FILL_NONE);
  }
  {
    cuuint64_t dims[3] = {192, 192, 1536};
    encode(&mapO, CU_TENSOR_MAP_DATA_TYPE_FLOAT32, 3, d_out,
           dims, strides, box, es,
           CU_TENSOR_MAP_INTERLEAVE_NONE, CU_TENSOR_MAP_SWIZZLE_NONE,
           CU_TENSOR_MAP_L2_PROMOTION_L2_128B, CU_TENSOR_MAP_FLOAT_OOB_FILL_NONE);
  }

  cudaFuncSetAttribute(winattn_tma3, cudaFuncAttributeMaxDynamicSharedMemorySize,
                       SMEM_BYTES);
  winattn_tma3<<<27648, 128, SMEM_BYTES>>>(mapQ, mapKV, mapO, mask);
}